// round 1
// baseline (speedup 1.0000x reference)
#include <cuda_runtime.h>
#include <math.h>

#define D_DIM 256
#define MAXB  64
#define MAXK  4096
#define BT    64     // tokens per GEMM block
#define KC    32     // k-chunk
#define TOPK_NT 1024

// scratch (no cudaMalloc allowed)
__device__ int g_sel[MAXB * MAXK];
__device__ int g_cnt[MAXB];

// ---------------- block scan (exclusive) for TOPK_NT=1024 ----------------
__device__ __forceinline__ void block_scan(int v, int& excl, int& total) {
    const int tid  = threadIdx.x;
    const int lane = tid & 31, wrp = tid >> 5;
    const int nw   = blockDim.x >> 5;
    __shared__ int wsum[32];
    int inc = v;
#pragma unroll
    for (int o = 1; o < 32; o <<= 1) {
        int n = __shfl_up_sync(0xFFFFFFFFu, inc, o);
        if (lane >= o) inc += n;
    }
    if (lane == 31) wsum[wrp] = inc;
    __syncthreads();
    if (wrp == 0) {
        int w = (lane < nw) ? wsum[lane] : 0;
#pragma unroll
        for (int o = 1; o < 32; o <<= 1) {
            int n = __shfl_up_sync(0xFFFFFFFFu, w, o);
            if (lane >= o) w += n;
        }
        wsum[lane] = w;
    }
    __syncthreads();
    int woff = wrp ? wsum[wrp - 1] : 0;
    excl  = woff + inc - v;
    total = wsum[nw - 1];
    __syncthreads();   // protect wsum before next call
}

// ---------------- top-k (radix select) + ordered compaction ----------------
// One block per batch row. Keys: float bits (all expr >= 0 => monotonic).
__global__ void topk_kernel(const float* __restrict__ expr, int B, int G, int K) {
    const int b   = blockIdx.x;
    const int tid = threadIdx.x;
    const int NT  = blockDim.x;
    const float* __restrict__ row = expr + (size_t)b * G;

    __shared__ unsigned int hist[256];
    __shared__ unsigned int s_prefix;
    __shared__ int s_remaining;
    __shared__ int s_eqcnt, s_outcnt;

    if (tid == 0) { s_prefix = 0u; s_remaining = K; }
    __syncthreads();

    // 4 passes of 8-bit radix select (find K-th largest key exactly)
    for (int pass = 0; pass < 4; ++pass) {
        const int shift = 24 - 8 * pass;
        const unsigned maskHigh = (pass == 0) ? 0u : (0xFFFFFFFFu << (shift + 8));
        for (int i = tid; i < 256; i += NT) hist[i] = 0u;
        __syncthreads();
        const unsigned prefix = s_prefix;
        for (int g = tid; g < G; g += NT) {
            unsigned key = __float_as_uint(row[g]);
            bool m = ((key & maskHigh) == prefix);
            unsigned act = __ballot_sync(0xFFFFFFFFu, m);
            if (m) {
                unsigned dig = (key >> shift) & 0xFFu;
                unsigned grp = __match_any_sync(act, dig);
                int leader = __ffs(grp) - 1;
                if ((tid & 31) == leader) atomicAdd(&hist[dig], (unsigned)__popc(grp));
            }
        }
        __syncthreads();
        if (tid == 0) {
            int rem = s_remaining;
            unsigned cum = 0; int sel = 0;
            for (int d = 255; d >= 0; --d) {
                unsigned c = hist[d];
                if (cum + c >= (unsigned)rem) { sel = d; s_remaining = rem - (int)cum; break; }
                cum += c;
            }
            s_prefix = prefix | ((unsigned)sel << shift);
        }
        __syncthreads();
    }
    const unsigned pivot = s_prefix;
    const int r = s_remaining;   // # of ==pivot to take (smallest indices first)

    if (tid == 0) { s_eqcnt = 0; s_outcnt = 0; }
    __syncthreads();

    // ordered stream compaction: keep if (key>pivot) or (key==pivot & eq-rank<r), and expr>0
    for (int base = 0; base < G; base += NT) {
        int g = base + tid;
        bool inb = (g < G);
        float fv = inb ? row[g] : 0.0f;
        unsigned key = __float_as_uint(fv);
        bool isgt = inb && (key > pivot);
        bool iseq = inb && (key == pivot);

        int eqbase = s_eqcnt, outbase = s_outcnt;  // stable since last sync
        int eqpre, eqtot;
        block_scan(iseq ? 1 : 0, eqpre, eqtot);
        bool keep = (isgt || (iseq && (eqbase + eqpre) < r)) && (fv > 0.0f);
        int kpre, ktot;
        block_scan(keep ? 1 : 0, kpre, ktot);
        if (keep) {
            int pos = outbase + kpre;
            if (pos < K) g_sel[b * MAXK + pos] = g;
        }
        __syncthreads();
        if (tid == 0) { s_eqcnt = eqbase + eqtot; s_outcnt = outbase + ktot; }
        __syncthreads();
    }
    if (tid == 0) g_cnt[b] = (s_outcnt < K) ? s_outcnt : K;
}

// ---------------- token GEMM + epilogue ----------------
// Block: 256 threads, tile = BT(=64) tokens x 256 outputs, K=256 in KC chunks.
// Thread (ty=tid/16, tx=tid%16) computes tokens ty*4..+3 x outputs {tx*4+64j}.
__global__ __launch_bounds__(256, 2)
void gemm_kernel(const float* __restrict__ expr,
                 const float* __restrict__ gene_emb,
                 const float* __restrict__ w1,
                 const float* __restrict__ b1,
                 const float* __restrict__ w2,
                 const float* __restrict__ b2,
                 float* __restrict__ out,
                 int B, int G, int K) {
    __shared__ float hA[KC][BT + 4];        // h^T: [k][t]
    __shared__ float ws[KC][D_DIM + 4];     // w2^T chunk: [k][e]
    __shared__ float sx[BT];
    __shared__ int   sg[BT];
    __shared__ float sw1[D_DIM], sb1[D_DIM], sb2[D_DIM];

    const int tid = threadIdx.x;
    const int tx = tid & 15, ty = tid >> 4;
    const int t0 = blockIdx.x * BT;

    if (tid < BT) {
        int tk = t0 + tid;
        int b = tk / K, k = tk - b * K;
        int g = -1; float x = 0.0f;
        if (b < B && k < g_cnt[b]) {
            g = g_sel[b * MAXK + k];
            x = expr[(size_t)b * G + g];
        }
        sg[tid] = g; sx[tid] = x;
    }
    sw1[tid] = w1[tid];
    sb1[tid] = b1[tid];
    sb2[tid] = b2[tid];
    __syncthreads();

    float4 acc[4][4];
#pragma unroll
    for (int i = 0; i < 4; ++i)
#pragma unroll
        for (int j = 0; j < 4; ++j) acc[i][j] = make_float4(0.f, 0.f, 0.f, 0.f);

    for (int kc = 0; kc < D_DIM / KC; ++kc) {
        // fill hA chunk: gelu(x*w1[d]+b1[d]) for d in this chunk, each computed once
#pragma unroll
        for (int i = 0; i < (KC * BT) / 256; ++i) {       // 8 per thread
            int lin = i * 256 + tid;
            int kk = lin >> 6, t = lin & 63;
            int d = kc * KC + kk;
            float z = fmaf(sx[t], sw1[d], sb1[d]);
            float h = 0.5f * z * (1.0f + erff(z * 0.70710678118654752f));
            hA[kk][t] = h;
        }
        // fill ws chunk (transpose w2 on the fly; global reads coalesced along d)
#pragma unroll
        for (int i = 0; i < (KC * D_DIM) / 256; ++i) {    // 32 per thread
            int lin = i * 256 + tid;
            int e = lin >> 5, dd = lin & 31;
            ws[dd][e] = w2[(size_t)e * D_DIM + kc * KC + dd];
        }
        __syncthreads();

#pragma unroll
        for (int kk = 0; kk < KC; ++kk) {
            float4 a = *(const float4*)(&hA[kk][ty * 4]);
            float4 bb[4];
#pragma unroll
            for (int j = 0; j < 4; ++j)
                bb[j] = *(const float4*)(&ws[kk][tx * 4 + 64 * j]);
            float av[4] = {a.x, a.y, a.z, a.w};
#pragma unroll
            for (int i = 0; i < 4; ++i)
#pragma unroll
                for (int j = 0; j < 4; ++j) {
                    acc[i][j].x = fmaf(av[i], bb[j].x, acc[i][j].x);
                    acc[i][j].y = fmaf(av[i], bb[j].y, acc[i][j].y);
                    acc[i][j].z = fmaf(av[i], bb[j].z, acc[i][j].z);
                    acc[i][j].w = fmaf(av[i], bb[j].w, acc[i][j].w);
                }
        }
        __syncthreads();
    }

    // epilogue: out = acc + gene_emb[g] + b2, or zeros for invalid slots
#pragma unroll
    for (int i = 0; i < 4; ++i) {
        int t = ty * 4 + i;
        int tk = t0 + t;
        int b = tk / K, k = tk - b * K;
        if (b >= B) continue;
        int g = sg[t];
        size_t rowoff = ((size_t)b * (K + 1) + (k + 1)) * D_DIM;
#pragma unroll
        for (int j = 0; j < 4; ++j) {
            int e = tx * 4 + 64 * j;
            float4 v;
            if (g >= 0) {
                float4 ge = *(const float4*)(&gene_emb[(size_t)g * D_DIM + e]);
                v.x = acc[i][j].x + ge.x + sb2[e + 0];
                v.y = acc[i][j].y + ge.y + sb2[e + 1];
                v.z = acc[i][j].z + ge.z + sb2[e + 2];
                v.w = acc[i][j].w + ge.w + sb2[e + 3];
            } else {
                v = make_float4(0.f, 0.f, 0.f, 0.f);
            }
            *(float4*)(&out[rowoff + e]) = v;
        }
    }
}

// ---------------- cls token + mask ----------------
__global__ void cls_mask_kernel(const float* __restrict__ cls,
                                float* __restrict__ out,
                                int B, int K, int hasMask) {
    const int b = blockIdx.x;
    const size_t rowsz = (size_t)(K + 1) * D_DIM;
    float* orow = out + (size_t)b * rowsz;
    for (int e = threadIdx.x; e < D_DIM; e += blockDim.x) orow[e] = cls[e];
    if (hasMask) {
        float* mask = out + (size_t)B * rowsz + (size_t)b * (K + 1);
        int cnt = g_cnt[b];
        for (int j = threadIdx.x; j < K + 1; j += blockDim.x)
            mask[j] = (j == 0 || (j - 1) < cnt) ? 1.0f : 0.0f;
    }
}

extern "C" void kernel_launch(void* const* d_in, const int* in_sizes, int n_in,
                              void* d_out, int out_size) {
    const float* expr     = (const float*)d_in[0];
    const float* gene_emb = (const float*)d_in[1];
    const float* w1       = (const float*)d_in[2];
    const float* b1       = (const float*)d_in[3];
    const float* w2       = (const float*)d_in[4];
    const float* b2       = (const float*)d_in[5];
    const float* cls      = (const float*)d_in[6];
    float* out = (float*)d_out;

    const int D = in_sizes[2];              // 256
    const int G = in_sizes[1] / D;          // 20000
    const int B = in_sizes[0] / G;          // 16

    // Output layout: tokens [B,K+1,D] (+ optional mask [B,K+1] as float, appended)
    long Kp1; int hasMask;
    if (out_size % ((long)B * (D + 1)) == 0) {
        Kp1 = out_size / ((long)B * (D + 1));
        hasMask = 1;
    } else {
        Kp1 = out_size / ((long)B * D);
        hasMask = 0;
    }
    const int K = (int)Kp1 - 1;             // 2048
    if (B > MAXB || K > MAXK || D != D_DIM) return;  // shapes fixed for this problem

    topk_kernel<<<B, TOPK_NT>>>(expr, B, G, K);

    int tiles = (B * K + BT - 1) / BT;
    gemm_kernel<<<tiles, 256>>>(expr, gene_emb, w1, b1, w2, b2, out, B, G, K);

    cls_mask_kernel<<<B, 256>>>(cls, out, B, K, hasMask);
}

// round 2
// speedup vs baseline: 1.3460x; 1.3460x over previous
#include <cuda_runtime.h>
#include <math.h>

#define D_DIM 256
#define MAXB  64
#define MAXK  4096
#define BT    64     // tokens per GEMM block
#define KC    32     // k-chunk
#define TOPK_NT 1024
#define SEG   20     // elements per thread in topk (TOPK_NT*SEG >= G)

// scratch (no cudaMalloc allowed)
__device__ int g_sel[MAXB * MAXK];
__device__ int g_cnt[MAXB];

// ---------------- block scan (exclusive) for TOPK_NT=1024 ----------------
__device__ __forceinline__ void block_scan(int v, int& excl, int& total) {
    const int tid  = threadIdx.x;
    const int lane = tid & 31, wrp = tid >> 5;
    const int nw   = blockDim.x >> 5;
    __shared__ int wsum[32];
    int inc = v;
#pragma unroll
    for (int o = 1; o < 32; o <<= 1) {
        int n = __shfl_up_sync(0xFFFFFFFFu, inc, o);
        if (lane >= o) inc += n;
    }
    if (lane == 31) wsum[wrp] = inc;
    __syncthreads();
    if (wrp == 0) {
        int w = (lane < nw) ? wsum[lane] : 0;
#pragma unroll
        for (int o = 1; o < 32; o <<= 1) {
            int n = __shfl_up_sync(0xFFFFFFFFu, w, o);
            if (lane >= o) w += n;
        }
        wsum[lane] = w;
    }
    __syncthreads();
    int woff = wrp ? wsum[wrp - 1] : 0;
    excl  = woff + inc - v;
    total = wsum[nw - 1];
    __syncthreads();   // protect wsum before next call
}

// ---------------- top-k (register-resident radix select) ----------------
// One block per batch row. Keys: float bits (all expr >= 0 => monotonic).
// Each thread owns a contiguous SEG-element segment, held in registers.
__global__ __launch_bounds__(TOPK_NT)
void topk_kernel(const float* __restrict__ expr, int B, int G, int K) {
    const int b   = blockIdx.x;
    const int tid = threadIdx.x;
    const float* __restrict__ row = expr + (size_t)b * G;

    __shared__ unsigned int hist[256];
    __shared__ unsigned int s_prefix;
    __shared__ int s_remaining;

    const int base = tid * SEG;
    unsigned keys[SEG];
    // load my segment (key 0 == value 0.0f for padding; never kept since expr>0 required)
    if (base + SEG <= G) {
#pragma unroll
        for (int i = 0; i < SEG; i += 4) {
            float4 v = *(const float4*)(&row[base + i]);
            keys[i + 0] = __float_as_uint(v.x);
            keys[i + 1] = __float_as_uint(v.y);
            keys[i + 2] = __float_as_uint(v.z);
            keys[i + 3] = __float_as_uint(v.w);
        }
    } else {
#pragma unroll
        for (int i = 0; i < SEG; ++i)
            keys[i] = (base + i < G) ? __float_as_uint(row[base + i]) : 0u;
    }

    if (tid == 0) { s_prefix = 0u; s_remaining = K; }
    __syncthreads();

    // 4 passes of 8-bit radix select (find K-th largest key exactly)
#pragma unroll
    for (int pass = 0; pass < 4; ++pass) {
        const int shift = 24 - 8 * pass;
        const unsigned maskHigh = (pass == 0) ? 0u : (0xFFFFFFFFu << (shift + 8));
        if (tid < 256) hist[tid] = 0u;
        __syncthreads();
        const unsigned prefix = s_prefix;
        const int rem = s_remaining;
#pragma unroll
        for (int i = 0; i < SEG; ++i) {
            unsigned key = keys[i];
            if ((key & maskHigh) == prefix)
                atomicAdd(&hist[(key >> shift) & 0xFFu], 1u);
        }
        __syncthreads();
        // parallel digit select: suffix sums over digits (descending) via block scan
        int v = (tid < 256) ? (int)hist[255 - tid] : 0;
        int excl, total;
        block_scan(v, excl, total);
        int incl = excl + v;
        if (tid < 256 && incl >= rem && excl < rem) {
            // unique crossing thread: digit = 255 - tid
            s_prefix    = prefix | ((unsigned)(255 - tid) << shift);
            s_remaining = rem - excl;
        }
        __syncthreads();
    }
    const unsigned pivot = s_prefix;
    const int r = s_remaining;   // # of ==pivot to keep (smallest gene indices first)

    // per-thread local counts
    int n_gt = 0, n_eq = 0;
#pragma unroll
    for (int i = 0; i < SEG; ++i) {
        n_gt += (keys[i] > pivot);
        n_eq += (keys[i] == pivot);
    }
    int eq_base, eq_tot;
    block_scan(n_eq, eq_base, eq_tot);
    int eq_keep = 0;
    if (pivot > 0u) {               // pivot==0 => eq elements have value 0, dropped by expr>0
        int take = r - eq_base;
        eq_keep = take < 0 ? 0 : (take > n_eq ? n_eq : take);
    }
    int n_keep = n_gt + eq_keep;
    int out_base, out_tot;
    block_scan(n_keep, out_base, out_tot);

    // sequential local emit (threads own ascending contiguous index ranges)
    int pos = out_base, erank = eq_base;
    int* __restrict__ sel = g_sel + b * MAXK;
#pragma unroll
    for (int i = 0; i < SEG; ++i) {
        unsigned key = keys[i];
        if (key > pivot) {
            sel[pos++] = base + i;
        } else if (key == pivot) {
            if (pivot > 0u && erank < r) sel[pos++] = base + i;
            ++erank;
        }
    }
    if (tid == 0) g_cnt[b] = (out_tot < K) ? out_tot : K;
}

// ---------------- token GEMM + epilogue ----------------
// Block: 256 threads, tile = BT(=64) tokens x 256 outputs, K=256 in KC chunks.
// Thread (ty=tid/16, tx=tid%16) computes tokens ty*4..+3 x outputs {tx*4+64j}.
__global__ __launch_bounds__(256, 2)
void gemm_kernel(const float* __restrict__ expr,
                 const float* __restrict__ gene_emb,
                 const float* __restrict__ w1,
                 const float* __restrict__ b1,
                 const float* __restrict__ w2,
                 const float* __restrict__ b2,
                 float* __restrict__ out,
                 int B, int G, int K) {
    __shared__ float hA[KC][BT + 4];        // h^T: [k][t]
    __shared__ float ws[KC][D_DIM + 4];     // w2^T chunk: [k][e]
    __shared__ float sx[BT];
    __shared__ int   sg[BT];
    __shared__ float sw1[D_DIM], sb1[D_DIM], sb2[D_DIM];

    const int tid = threadIdx.x;
    const int tx = tid & 15, ty = tid >> 4;
    const int t0 = blockIdx.x * BT;

    if (tid < BT) {
        int tk = t0 + tid;
        int b = tk / K, k = tk - b * K;
        int g = -1; float x = 0.0f;
        if (b < B && k < g_cnt[b]) {
            g = g_sel[b * MAXK + k];
            x = expr[(size_t)b * G + g];
        }
        sg[tid] = g; sx[tid] = x;
    }
    sw1[tid] = w1[tid];
    sb1[tid] = b1[tid];
    sb2[tid] = b2[tid];
    __syncthreads();

    float4 acc[4][4];
#pragma unroll
    for (int i = 0; i < 4; ++i)
#pragma unroll
        for (int j = 0; j < 4; ++j) acc[i][j] = make_float4(0.f, 0.f, 0.f, 0.f);

    for (int kc = 0; kc < D_DIM / KC; ++kc) {
        // fill hA chunk: gelu(x*w1[d]+b1[d]) for d in this chunk, each computed once
#pragma unroll
        for (int i = 0; i < (KC * BT) / 256; ++i) {       // 8 per thread
            int lin = i * 256 + tid;
            int kk = lin >> 6, t = lin & 63;
            int d = kc * KC + kk;
            float z = fmaf(sx[t], sw1[d], sb1[d]);
            float h = 0.5f * z * (1.0f + erff(z * 0.70710678118654752f));
            hA[kk][t] = h;
        }
        // fill ws chunk (transpose w2 on the fly; global reads coalesced along d)
#pragma unroll
        for (int i = 0; i < (KC * D_DIM) / 256; ++i) {    // 32 per thread
            int lin = i * 256 + tid;
            int e = lin >> 5, dd = lin & 31;
            ws[dd][e] = w2[(size_t)e * D_DIM + kc * KC + dd];
        }
        __syncthreads();

#pragma unroll
        for (int kk = 0; kk < KC; ++kk) {
            float4 a = *(const float4*)(&hA[kk][ty * 4]);
            float4 bb[4];
#pragma unroll
            for (int j = 0; j < 4; ++j)
                bb[j] = *(const float4*)(&ws[kk][tx * 4 + 64 * j]);
            float av[4] = {a.x, a.y, a.z, a.w};
#pragma unroll
            for (int i = 0; i < 4; ++i)
#pragma unroll
                for (int j = 0; j < 4; ++j) {
                    acc[i][j].x = fmaf(av[i], bb[j].x, acc[i][j].x);
                    acc[i][j].y = fmaf(av[i], bb[j].y, acc[i][j].y);
                    acc[i][j].z = fmaf(av[i], bb[j].z, acc[i][j].z);
                    acc[i][j].w = fmaf(av[i], bb[j].w, acc[i][j].w);
                }
        }
        __syncthreads();
    }

    // epilogue: out = acc + gene_emb[g] + b2, or zeros for invalid slots
#pragma unroll
    for (int i = 0; i < 4; ++i) {
        int t = ty * 4 + i;
        int tk = t0 + t;
        int b = tk / K, k = tk - b * K;
        if (b >= B) continue;
        int g = sg[t];
        size_t rowoff = ((size_t)b * (K + 1) + (k + 1)) * D_DIM;
#pragma unroll
        for (int j = 0; j < 4; ++j) {
            int e = tx * 4 + 64 * j;
            float4 v;
            if (g >= 0) {
                float4 ge = *(const float4*)(&gene_emb[(size_t)g * D_DIM + e]);
                v.x = acc[i][j].x + ge.x + sb2[e + 0];
                v.y = acc[i][j].y + ge.y + sb2[e + 1];
                v.z = acc[i][j].z + ge.z + sb2[e + 2];
                v.w = acc[i][j].w + ge.w + sb2[e + 3];
            } else {
                v = make_float4(0.f, 0.f, 0.f, 0.f);
            }
            *(float4*)(&out[rowoff + e]) = v;
        }
    }
}

// ---------------- cls token + mask ----------------
__global__ void cls_mask_kernel(const float* __restrict__ cls,
                                float* __restrict__ out,
                                int B, int K, int hasMask) {
    const int b = blockIdx.x;
    const size_t rowsz = (size_t)(K + 1) * D_DIM;
    float* orow = out + (size_t)b * rowsz;
    for (int e = threadIdx.x; e < D_DIM; e += blockDim.x) orow[e] = cls[e];
    if (hasMask) {
        float* mask = out + (size_t)B * rowsz + (size_t)b * (K + 1);
        int cnt = g_cnt[b];
        for (int j = threadIdx.x; j < K + 1; j += blockDim.x)
            mask[j] = (j == 0 || (j - 1) < cnt) ? 1.0f : 0.0f;
    }
}

extern "C" void kernel_launch(void* const* d_in, const int* in_sizes, int n_in,
                              void* d_out, int out_size) {
    const float* expr     = (const float*)d_in[0];
    const float* gene_emb = (const float*)d_in[1];
    const float* w1       = (const float*)d_in[2];
    const float* b1       = (const float*)d_in[3];
    const float* w2       = (const float*)d_in[4];
    const float* b2       = (const float*)d_in[5];
    const float* cls      = (const float*)d_in[6];
    float* out = (float*)d_out;

    const int D = in_sizes[2];              // 256
    const int G = in_sizes[1] / D;          // 20000
    const int B = in_sizes[0] / G;          // 16

    // Output layout: tokens [B,K+1,D] (+ optional mask [B,K+1] as float, appended)
    long Kp1; int hasMask;
    if (out_size % ((long)B * (D + 1)) == 0) {
        Kp1 = out_size / ((long)B * (D + 1));
        hasMask = 1;
    } else {
        Kp1 = out_size / ((long)B * D);
        hasMask = 0;
    }
    const int K = (int)Kp1 - 1;             // 2048
    if (B > MAXB || K > MAXK || D != D_DIM) return;  // shapes fixed for this problem
    if (TOPK_NT * SEG < G) return;          // topk capacity (20480 >= 20000)

    topk_kernel<<<B, TOPK_NT>>>(expr, B, G, K);

    int tiles = (B * K + BT - 1) / BT;
    gemm_kernel<<<tiles, 256>>>(expr, gene_emb, w1, b1, w2, b2, out, B, G, K);

    cls_mask_kernel<<<B, 256>>>(cls, out, B, K, hasMask);
}

// round 3
// speedup vs baseline: 1.4077x; 1.0459x over previous
#include <cuda_runtime.h>
#include <math.h>

#define D_DIM 256
#define MAXB  64
#define MAXK  4096
#define BT    64     // tokens per GEMM block
#define KC    32     // k-chunk
#define TOPK_NT 1024
#define SEG   20     // elements per thread in topk (TOPK_NT*SEG >= G)

// scratch (no cudaMalloc allowed)
__device__ int g_sel[MAXB * MAXK];
__device__ int g_cnt[MAXB];

// ---------------- packed f32x2 helpers (SASS FFMA2) ----------------
__device__ __forceinline__ unsigned long long pk2(float lo, float hi) {
    unsigned long long r;
    asm("mov.b64 %0, {%1, %2};" : "=l"(r) : "f"(lo), "f"(hi));
    return r;
}
__device__ __forceinline__ void fma2(unsigned long long& acc,
                                     unsigned long long a, unsigned long long b) {
    asm("fma.rn.f32x2 %0, %1, %2, %0;" : "+l"(acc) : "l"(a), "l"(b));
}
__device__ __forceinline__ void upk2(unsigned long long v, float& lo, float& hi) {
    asm("mov.b64 {%0, %1}, %2;" : "=f"(lo), "=f"(hi) : "l"(v));
}

// ---------------- block scan (exclusive) ----------------
__device__ __forceinline__ void block_scan(int v, int& excl, int& total) {
    const int tid  = threadIdx.x;
    const int lane = tid & 31, wrp = tid >> 5;
    const int nw   = blockDim.x >> 5;
    __shared__ int wsum[32];
    int inc = v;
#pragma unroll
    for (int o = 1; o < 32; o <<= 1) {
        int n = __shfl_up_sync(0xFFFFFFFFu, inc, o);
        if (lane >= o) inc += n;
    }
    if (lane == 31) wsum[wrp] = inc;
    __syncthreads();
    if (wrp == 0) {
        int w = (lane < nw) ? wsum[lane] : 0;
#pragma unroll
        for (int o = 1; o < 32; o <<= 1) {
            int n = __shfl_up_sync(0xFFFFFFFFu, w, o);
            if (lane >= o) w += n;
        }
        wsum[lane] = w;
    }
    __syncthreads();
    int woff = wrp ? wsum[wrp - 1] : 0;
    excl  = woff + inc - v;
    total = wsum[nw - 1];
    __syncthreads();   // protect wsum before next call
}

// ---------------- top-k (register-resident radix select) ----------------
__global__ __launch_bounds__(TOPK_NT)
void topk_kernel(const float* __restrict__ expr, int B, int G, int K) {
    const int b   = blockIdx.x;
    const int tid = threadIdx.x;
    const float* __restrict__ row = expr + (size_t)b * G;

    __shared__ unsigned int hist[256];
    __shared__ unsigned int s_prefix;
    __shared__ int s_remaining;

    const int base = tid * SEG;
    unsigned keys[SEG];
    if (base + SEG <= G) {
#pragma unroll
        for (int i = 0; i < SEG; i += 4) {
            float4 v = *(const float4*)(&row[base + i]);
            keys[i + 0] = __float_as_uint(v.x);
            keys[i + 1] = __float_as_uint(v.y);
            keys[i + 2] = __float_as_uint(v.z);
            keys[i + 3] = __float_as_uint(v.w);
        }
    } else {
#pragma unroll
        for (int i = 0; i < SEG; ++i)
            keys[i] = (base + i < G) ? __float_as_uint(row[base + i]) : 0u;
    }

    if (tid == 0) { s_prefix = 0u; s_remaining = K; }
    __syncthreads();

#pragma unroll
    for (int pass = 0; pass < 4; ++pass) {
        const int shift = 24 - 8 * pass;
        const unsigned maskHigh = (pass == 0) ? 0u : (0xFFFFFFFFu << (shift + 8));
        if (tid < 256) hist[tid] = 0u;
        __syncthreads();
        const unsigned prefix = s_prefix;
        const int rem = s_remaining;
#pragma unroll
        for (int i = 0; i < SEG; ++i) {
            unsigned key = keys[i];
            if ((key & maskHigh) == prefix)
                atomicAdd(&hist[(key >> shift) & 0xFFu], 1u);
        }
        __syncthreads();
        int v = (tid < 256) ? (int)hist[255 - tid] : 0;
        int excl, total;
        block_scan(v, excl, total);
        int incl = excl + v;
        if (tid < 256 && incl >= rem && excl < rem) {
            s_prefix    = prefix | ((unsigned)(255 - tid) << shift);
            s_remaining = rem - excl;
        }
        __syncthreads();
    }
    const unsigned pivot = s_prefix;
    const int r = s_remaining;

    int n_gt = 0, n_eq = 0;
#pragma unroll
    for (int i = 0; i < SEG; ++i) {
        n_gt += (keys[i] > pivot);
        n_eq += (keys[i] == pivot);
    }
    int eq_base, eq_tot;
    block_scan(n_eq, eq_base, eq_tot);
    int eq_keep = 0;
    if (pivot > 0u) {
        int take = r - eq_base;
        eq_keep = take < 0 ? 0 : (take > n_eq ? n_eq : take);
    }
    int n_keep = n_gt + eq_keep;
    int out_base, out_tot;
    block_scan(n_keep, out_base, out_tot);

    int pos = out_base, erank = eq_base;
    int* __restrict__ sel = g_sel + b * MAXK;
#pragma unroll
    for (int i = 0; i < SEG; ++i) {
        unsigned key = keys[i];
        if (key > pivot) {
            sel[pos++] = base + i;
        } else if (key == pivot) {
            if (pivot > 0u && erank < r) sel[pos++] = base + i;
            ++erank;
        }
    }
    if (tid == 0) g_cnt[b] = (out_tot < K) ? out_tot : K;
}

// ---------------- token GEMM + epilogue (FFMA2 packed fp32) ----------------
// Block: 256 threads = 8 ty x 32 tx. Tile = 64 tokens x 256 outputs.
// Thread tile: tokens {ty*4+i, 32+ty*4+i} x outputs {tx*4+j, 128+tx*4+j} = 8x8.
__global__ __launch_bounds__(256, 2)
void gemm_kernel(const float* __restrict__ expr,
                 const float* __restrict__ gene_emb,
                 const float* __restrict__ w1,
                 const float* __restrict__ b1,
                 const float* __restrict__ w2,
                 const float* __restrict__ b2,
                 float* __restrict__ out,
                 int B, int G, int K) {
    __shared__ float hA[KC][BT + 4];        // h^T: [k][t]
    __shared__ float ws[KC][D_DIM + 4];     // w2^T chunk: [k][e]
    __shared__ float sx[BT];
    __shared__ int   sg[BT];
    __shared__ float sw1[D_DIM], sb1[D_DIM], sb2[D_DIM];

    const int tid = threadIdx.x;
    const int tx = tid & 31, ty = tid >> 5;
    const int t0 = blockIdx.x * BT;

    if (tid < BT) {
        int tk = t0 + tid;
        int b = tk / K, k = tk - b * K;
        int g = -1; float x = 0.0f;
        if (b < B && k < g_cnt[b]) {
            g = g_sel[b * MAXK + k];
            x = expr[(size_t)b * G + g];
        }
        sg[tid] = g; sx[tid] = x;
    }
    sw1[tid] = w1[tid];
    sb1[tid] = b1[tid];
    sb2[tid] = b2[tid];
    __syncthreads();

    unsigned long long acc[8][4];   // [token][output-pair]; each u64 = 2 fp32
#pragma unroll
    for (int i = 0; i < 8; ++i)
#pragma unroll
        for (int j = 0; j < 4; ++j) acc[i][j] = 0ull;

    for (int kc = 0; kc < D_DIM / KC; ++kc) {
        // fill hA chunk: gelu(x*w1[d]+b1[d]), each computed once per block
#pragma unroll
        for (int i = 0; i < (KC * BT) / 256; ++i) {       // 8 per thread
            int lin = i * 256 + tid;
            int kk = lin >> 6, t = lin & 63;
            int d = kc * KC + kk;
            float z = fmaf(sx[t], sw1[d], sb1[d]);
            float h = 0.5f * z * (1.0f + erff(z * 0.70710678118654752f));
            hA[kk][t] = h;
        }
        // fill ws chunk (transpose w2 on the fly)
#pragma unroll
        for (int i = 0; i < (KC * D_DIM) / 256; ++i) {    // 32 per thread
            int lin = i * 256 + tid;
            int e = lin >> 5, dd = lin & 31;
            ws[dd][e] = w2[(size_t)e * D_DIM + kc * KC + dd];
        }
        __syncthreads();

#pragma unroll
        for (int kk = 0; kk < KC; ++kk) {
            float4 a0 = *(const float4*)(&hA[kk][ty * 4]);        // broadcast in warp
            float4 a1 = *(const float4*)(&hA[kk][32 + ty * 4]);   // broadcast in warp
            float4 b0 = *(const float4*)(&ws[kk][tx * 4]);        // coalesced
            float4 b1 = *(const float4*)(&ws[kk][128 + tx * 4]);  // coalesced
            unsigned long long bp[4] = {
                pk2(b0.x, b0.y), pk2(b0.z, b0.w),
                pk2(b1.x, b1.y), pk2(b1.z, b1.w)
            };
            float at[8] = {a0.x, a0.y, a0.z, a0.w, a1.x, a1.y, a1.z, a1.w};
#pragma unroll
            for (int t = 0; t < 8; ++t) {
                unsigned long long ap = pk2(at[t], at[t]);
#pragma unroll
                for (int j = 0; j < 4; ++j) fma2(acc[t][j], ap, bp[j]);
            }
        }
        __syncthreads();
    }

    // epilogue: out = acc + gene_emb[g] + b2, or zeros for invalid slots
#pragma unroll
    for (int t = 0; t < 8; ++t) {
        int tt = (t < 4) ? (ty * 4 + t) : (32 + ty * 4 + (t - 4));
        int tk = t0 + tt;
        int b = tk / K, k = tk - b * K;
        if (b >= B) continue;
        int g = sg[tt];
        size_t rowoff = ((size_t)b * (K + 1) + (k + 1)) * D_DIM;
#pragma unroll
        for (int half = 0; half < 2; ++half) {
            int e = half * 128 + tx * 4;
            float4 v;
            if (g >= 0) {
                float a, bq, c, dq;
                upk2(acc[t][half * 2 + 0], a, bq);
                upk2(acc[t][half * 2 + 1], c, dq);
                float4 ge = *(const float4*)(&gene_emb[(size_t)g * D_DIM + e]);
                v.x = a  + ge.x + sb2[e + 0];
                v.y = bq + ge.y + sb2[e + 1];
                v.z = c  + ge.z + sb2[e + 2];
                v.w = dq + ge.w + sb2[e + 3];
            } else {
                v = make_float4(0.f, 0.f, 0.f, 0.f);
            }
            *(float4*)(&out[rowoff + e]) = v;
        }
    }
}

// ---------------- cls token + mask ----------------
__global__ void cls_mask_kernel(const float* __restrict__ cls,
                                float* __restrict__ out,
                                int B, int K, int hasMask) {
    const int b = blockIdx.x;
    const size_t rowsz = (size_t)(K + 1) * D_DIM;
    float* orow = out + (size_t)b * rowsz;
    for (int e = threadIdx.x; e < D_DIM; e += blockDim.x) orow[e] = cls[e];
    if (hasMask) {
        float* mask = out + (size_t)B * rowsz + (size_t)b * (K + 1);
        int cnt = g_cnt[b];
        for (int j = threadIdx.x; j < K + 1; j += blockDim.x)
            mask[j] = (j == 0 || (j - 1) < cnt) ? 1.0f : 0.0f;
    }
}

extern "C" void kernel_launch(void* const* d_in, const int* in_sizes, int n_in,
                              void* d_out, int out_size) {
    const float* expr     = (const float*)d_in[0];
    const float* gene_emb = (const float*)d_in[1];
    const float* w1       = (const float*)d_in[2];
    const float* b1       = (const float*)d_in[3];
    const float* w2       = (const float*)d_in[4];
    const float* b2       = (const float*)d_in[5];
    const float* cls      = (const float*)d_in[6];
    float* out = (float*)d_out;

    const int D = in_sizes[2];              // 256
    const int G = in_sizes[1] / D;          // 20000
    const int B = in_sizes[0] / G;          // 16

    long Kp1; int hasMask;
    if (out_size % ((long)B * (D + 1)) == 0) {
        Kp1 = out_size / ((long)B * (D + 1));
        hasMask = 1;
    } else {
        Kp1 = out_size / ((long)B * D);
        hasMask = 0;
    }
    const int K = (int)Kp1 - 1;             // 2048
    if (B > MAXB || K > MAXK || D != D_DIM) return;
    if (TOPK_NT * SEG < G) return;

    topk_kernel<<<B, TOPK_NT>>>(expr, B, G, K);

    int tiles = (B * K + BT - 1) / BT;
    gemm_kernel<<<tiles, 256>>>(expr, gene_emb, w1, b1, w2, b2, out, B, G, K);

    cls_mask_kernel<<<B, 256>>>(cls, out, B, K, hasMask);
}

// round 7
// speedup vs baseline: 2.3859x; 1.6948x over previous
#include <cuda_runtime.h>
#include <cuda_bf16.h>
#include <math.h>
#include <stdint.h>

#define D_DIM 256
#define MAXB  64
#define MAXK  4096
#define TOPK_NT 1024
#define SEG   20

#define MT    64                  // tokens per GEMM block
#define KC    64                  // K elements per chunk
#define NCHUNK (D_DIM / KC)       // 4
#define APITCH 72                 // bf16 elems per A row in smem
#define BPITCH 72
#define A_ELEMS (MT * APITCH)     // 4608
#define B_ELEMS (D_DIM * BPITCH)  // 18432
#define SM_AHI 0
#define SM_ALO (A_ELEMS)
#define SM_BHI (2 * A_ELEMS)
#define SM_BLO (2 * A_ELEMS + B_ELEMS)
#define DYN_ELEMS (2 * A_ELEMS + 2 * B_ELEMS)      // 46080 bf16
#define DYN_BYTES (DYN_ELEMS * 2)                  // 92160 B

// scratch (no cudaMalloc allowed)
__device__ int g_sel[MAXB * MAXK];
__device__ int g_cnt[MAXB];
__device__ __nv_bfloat16 g_w2hi[D_DIM * D_DIM];
__device__ __nv_bfloat16 g_w2lo[D_DIM * D_DIM];

// ---------------- mma.sync helper (portable PTX, maps to HMMA) ----------------
__device__ __forceinline__ void mma_bf16(float* c, const uint32_t* a, const uint32_t* b) {
    asm volatile(
        "mma.sync.aligned.m16n8k16.row.col.f32.bf16.bf16.f32 "
        "{%0,%1,%2,%3}, {%4,%5,%6,%7}, {%8,%9}, {%0,%1,%2,%3};"
        : "+f"(c[0]), "+f"(c[1]), "+f"(c[2]), "+f"(c[3])
        : "r"(a[0]), "r"(a[1]), "r"(a[2]), "r"(a[3]), "r"(b[0]), "r"(b[1]));
}

// ---------------- block scan (exclusive) ----------------
__device__ __forceinline__ void block_scan(int v, int& excl, int& total) {
    const int tid  = threadIdx.x;
    const int lane = tid & 31, wrp = tid >> 5;
    const int nw   = blockDim.x >> 5;
    __shared__ int wsum[32];
    int inc = v;
#pragma unroll
    for (int o = 1; o < 32; o <<= 1) {
        int n = __shfl_up_sync(0xFFFFFFFFu, inc, o);
        if (lane >= o) inc += n;
    }
    if (lane == 31) wsum[wrp] = inc;
    __syncthreads();
    if (wrp == 0) {
        int w = (lane < nw) ? wsum[lane] : 0;
#pragma unroll
        for (int o = 1; o < 32; o <<= 1) {
            int n = __shfl_up_sync(0xFFFFFFFFu, w, o);
            if (lane >= o) w += n;
        }
        wsum[lane] = w;
    }
    __syncthreads();
    int woff = wrp ? wsum[wrp - 1] : 0;
    excl  = woff + inc - v;
    total = wsum[nw - 1];
    __syncthreads();
}

// ---------------- top-k (register-resident radix select) ----------------
__global__ __launch_bounds__(TOPK_NT)
void topk_kernel(const float* __restrict__ expr, int B, int G, int K) {
    const int b   = blockIdx.x;
    const int tid = threadIdx.x;
    const float* __restrict__ row = expr + (size_t)b * G;

    __shared__ unsigned int hist[256];
    __shared__ unsigned int s_prefix;
    __shared__ int s_remaining;

    const int base = tid * SEG;
    unsigned keys[SEG];
    if (base + SEG <= G) {
#pragma unroll
        for (int i = 0; i < SEG; i += 4) {
            float4 v = *(const float4*)(&row[base + i]);
            keys[i + 0] = __float_as_uint(v.x);
            keys[i + 1] = __float_as_uint(v.y);
            keys[i + 2] = __float_as_uint(v.z);
            keys[i + 3] = __float_as_uint(v.w);
        }
    } else {
#pragma unroll
        for (int i = 0; i < SEG; ++i)
            keys[i] = (base + i < G) ? __float_as_uint(row[base + i]) : 0u;
    }

    if (tid == 0) { s_prefix = 0u; s_remaining = K; }
    __syncthreads();

#pragma unroll
    for (int pass = 0; pass < 4; ++pass) {
        const int shift = 24 - 8 * pass;
        const unsigned maskHigh = (pass == 0) ? 0u : (0xFFFFFFFFu << (shift + 8));
        if (tid < 256) hist[tid] = 0u;
        __syncthreads();
        const unsigned prefix = s_prefix;
        const int rem = s_remaining;
#pragma unroll
        for (int i = 0; i < SEG; ++i) {
            unsigned key = keys[i];
            if ((key & maskHigh) == prefix)
                atomicAdd(&hist[(key >> shift) & 0xFFu], 1u);
        }
        __syncthreads();
        int v = (tid < 256) ? (int)hist[255 - tid] : 0;
        int excl, total;
        block_scan(v, excl, total);
        int incl = excl + v;
        if (tid < 256 && incl >= rem && excl < rem) {
            s_prefix    = prefix | ((unsigned)(255 - tid) << shift);
            s_remaining = rem - excl;
        }
        __syncthreads();
    }
    const unsigned pivot = s_prefix;
    const int r = s_remaining;

    int n_gt = 0, n_eq = 0;
#pragma unroll
    for (int i = 0; i < SEG; ++i) {
        n_gt += (keys[i] > pivot);
        n_eq += (keys[i] == pivot);
    }
    int eq_base, eq_tot;
    block_scan(n_eq, eq_base, eq_tot);
    int eq_keep = 0;
    if (pivot > 0u) {
        int take = r - eq_base;
        eq_keep = take < 0 ? 0 : (take > n_eq ? n_eq : take);
    }
    int n_keep = n_gt + eq_keep;
    int out_base, out_tot;
    block_scan(n_keep, out_base, out_tot);

    int pos = out_base, erank = eq_base;
    int* __restrict__ sel = g_sel + b * MAXK;
#pragma unroll
    for (int i = 0; i < SEG; ++i) {
        unsigned key = keys[i];
        if (key > pivot) {
            sel[pos++] = base + i;
        } else if (key == pivot) {
            if (pivot > 0u && erank < r) sel[pos++] = base + i;
            ++erank;
        }
    }
    if (tid == 0) g_cnt[b] = (out_tot < K) ? out_tot : K;
}

// ---------------- precompute w2 hi/lo bf16 split ----------------
__global__ void w2split_kernel(const float* __restrict__ w2) {
    int i = blockIdx.x * blockDim.x + threadIdx.x;   // 65536 threads
    float w = w2[i];
    __nv_bfloat16 hi = __float2bfloat16(w);
    float lo_f = w - __bfloat162float(hi);
    g_w2hi[i] = hi;
    g_w2lo[i] = __float2bfloat16(lo_f);
}

// ---------------- token GEMM via mma.sync bf16 (3-pass hi/lo) ----------------
// Block: 256 threads = 8 warps (2 x 4). Block tile 64 tokens x 256 outputs.
// Warp tile: 32 tokens x 64 outputs. K = 256 in 4 chunks of 64.
__global__ __launch_bounds__(256, 2)
void gemm_kernel(const float* __restrict__ expr,
                 const float* __restrict__ gene_emb,
                 const float* __restrict__ w1,
                 const float* __restrict__ b1,
                 const float* __restrict__ b2,
                 float* __restrict__ out,
                 int B, int G, int K) {
    extern __shared__ __nv_bfloat16 sm[];
    __nv_bfloat16* const sAhi = sm + SM_AHI;
    __nv_bfloat16* const sAlo = sm + SM_ALO;
    __nv_bfloat16* const sBhi = sm + SM_BHI;
    __nv_bfloat16* const sBlo = sm + SM_BLO;

    __shared__ float sx[MT];
    __shared__ int   sgm[MT];
    __shared__ float sw1[D_DIM], sb1[D_DIM], sb2[D_DIM];

    const int tid  = threadIdx.x;
    const int wid  = tid >> 5, lane = tid & 31;
    const int wm   = wid >> 2;            // 0..1 (token dim)
    const int wn   = wid & 3;             // 0..3 (output dim)
    const int gr   = lane >> 2;           // groupID 0..7
    const int cq   = lane & 3;            // threadID-in-group
    const int t0   = blockIdx.x * MT;
    const int bb   = t0 / K;              // K % MT == 0

    if (tid < MT) {
        int k = t0 - bb * K + tid;
        int g = -1; float x = 0.0f;
        if (bb < B && k < g_cnt[bb]) {
            g = g_sel[bb * MAXK + k];
            x = expr[(size_t)bb * G + g];
        }
        sgm[tid] = g; sx[tid] = x;
    }
    sw1[tid] = w1[tid];
    sb1[tid] = b1[tid];
    sb2[tid] = b2[tid];
    __syncthreads();

    float acc[2][8][4];
#pragma unroll
    for (int mi = 0; mi < 2; ++mi)
#pragma unroll
        for (int ni = 0; ni < 8; ++ni)
#pragma unroll
            for (int j = 0; j < 4; ++j) acc[mi][ni][j] = 0.0f;

    const int at = tid >> 2;              // token row for A fill (0..63)
    const int akq = tid & 3;              // k quarter (16 elems)
    const float ax = sx[at];

    for (int c = 0; c < NCHUNK; ++c) {
        const int d0 = c * KC;
        // --- A fill: h = gelu(x*w1+b1), split hi/lo. 16 elems/thread ---
#pragma unroll
        for (int j = 0; j < 16; ++j) {
            int kk = akq * 16 + j;
            int d  = d0 + kk;
            float z = fmaf(ax, sw1[d], sb1[d]);
            float h = 0.5f * z * (1.0f + erff(z * 0.70710678118654752f));
            __nv_bfloat16 hi = __float2bfloat16(h);
            float lo_f = h - __bfloat162float(hi);
            sAhi[at * APITCH + kk] = hi;
            sAlo[at * APITCH + kk] = __float2bfloat16(lo_f);
        }
        // --- B fill: copy precomputed w2 hi/lo chunk. [n][k] layout ---
#pragma unroll
        for (int i = 0; i < 8; ++i) {
            int n   = i * 32 + (tid >> 3);
            int k16 = (tid & 7) * 8;      // 8 bf16 = 16 B
            uint4 vhi = *(const uint4*)(&g_w2hi[(size_t)n * D_DIM + d0 + k16]);
            uint4 vlo = *(const uint4*)(&g_w2lo[(size_t)n * D_DIM + d0 + k16]);
            *(uint4*)(&sBhi[n * BPITCH + k16]) = vhi;
            *(uint4*)(&sBlo[n * BPITCH + k16]) = vlo;
        }
        __syncthreads();

        // --- mainloop: 4 k-steps of 16 ---
#pragma unroll
        for (int ks = 0; ks < 4; ++ks) {
            const int kb = ks * 16;
            uint32_t ahi[2][4], alo[2][4];
#pragma unroll
            for (int mi = 0; mi < 2; ++mi) {
                int r0 = (wm * 32 + mi * 16 + gr) * APITCH + kb + 2 * cq;
                int r1 = r0 + 8 * APITCH;
                ahi[mi][0] = *(const uint32_t*)(&sAhi[r0]);
                ahi[mi][1] = *(const uint32_t*)(&sAhi[r1]);
                ahi[mi][2] = *(const uint32_t*)(&sAhi[r0 + 8]);
                ahi[mi][3] = *(const uint32_t*)(&sAhi[r1 + 8]);
                alo[mi][0] = *(const uint32_t*)(&sAlo[r0]);
                alo[mi][1] = *(const uint32_t*)(&sAlo[r1]);
                alo[mi][2] = *(const uint32_t*)(&sAlo[r0 + 8]);
                alo[mi][3] = *(const uint32_t*)(&sAlo[r1 + 8]);
            }
#pragma unroll
            for (int ni = 0; ni < 8; ++ni) {
                int nrow = (wn * 64 + ni * 8 + gr) * BPITCH + kb + 2 * cq;
                uint32_t bhi[2], blo[2];
                bhi[0] = *(const uint32_t*)(&sBhi[nrow]);
                bhi[1] = *(const uint32_t*)(&sBhi[nrow + 8]);
                blo[0] = *(const uint32_t*)(&sBlo[nrow]);
                blo[1] = *(const uint32_t*)(&sBlo[nrow + 8]);
#pragma unroll
                for (int mi = 0; mi < 2; ++mi) {
                    mma_bf16(acc[mi][ni], ahi[mi], bhi);
                    mma_bf16(acc[mi][ni], ahi[mi], blo);
                    mma_bf16(acc[mi][ni], alo[mi], bhi);
                }
            }
        }
        __syncthreads();
    }

    // ---------------- epilogue ----------------
#pragma unroll
    for (int mi = 0; mi < 2; ++mi) {
#pragma unroll
        for (int half = 0; half < 2; ++half) {
            int t_local = wm * 32 + mi * 16 + gr + half * 8;
            int g = sgm[t_local];
            int tk = t0 + t_local;
            int k_in = tk - bb * K;
            size_t rowoff = ((size_t)bb * (K + 1) + (k_in + 1)) * D_DIM;
#pragma unroll
            for (int ni = 0; ni < 8; ++ni) {
                int e = wn * 64 + ni * 8 + 2 * cq;
                float c0 = acc[mi][ni][half * 2 + 0];
                float c1 = acc[mi][ni][half * 2 + 1];
                float2 v;
                if (g >= 0) {
                    float2 ge = *(const float2*)(&gene_emb[(size_t)g * D_DIM + e]);
                    v.x = c0 + ge.x + sb2[e + 0];
                    v.y = c1 + ge.y + sb2[e + 1];
                } else {
                    v = make_float2(0.f, 0.f);
                }
                *(float2*)(&out[rowoff + e]) = v;
            }
        }
    }
}

// ---------------- cls token + mask ----------------
__global__ void cls_mask_kernel(const float* __restrict__ cls,
                                float* __restrict__ out,
                                int B, int K, int hasMask) {
    const int b = blockIdx.x;
    const size_t rowsz = (size_t)(K + 1) * D_DIM;
    float* orow = out + (size_t)b * rowsz;
    for (int e = threadIdx.x; e < D_DIM; e += blockDim.x) orow[e] = cls[e];
    if (hasMask) {
        float* mask = out + (size_t)B * rowsz + (size_t)b * (K + 1);
        int cnt = g_cnt[b];
        for (int j = threadIdx.x; j < K + 1; j += blockDim.x)
            mask[j] = (j == 0 || (j - 1) < cnt) ? 1.0f : 0.0f;
    }
}

extern "C" void kernel_launch(void* const* d_in, const int* in_sizes, int n_in,
                              void* d_out, int out_size) {
    const float* expr     = (const float*)d_in[0];
    const float* gene_emb = (const float*)d_in[1];
    const float* w1       = (const float*)d_in[2];
    const float* b1       = (const float*)d_in[3];
    const float* w2       = (const float*)d_in[4];
    const float* b2       = (const float*)d_in[5];
    const float* cls      = (const float*)d_in[6];
    float* out = (float*)d_out;

    const int D = in_sizes[2];              // 256
    const int G = in_sizes[1] / D;          // 20000
    const int B = in_sizes[0] / G;          // 16

    long Kp1; int hasMask;
    if (out_size % ((long)B * (D + 1)) == 0) {
        Kp1 = out_size / ((long)B * (D + 1));
        hasMask = 1;
    } else {
        Kp1 = out_size / ((long)B * D);
        hasMask = 0;
    }
    const int K = (int)Kp1 - 1;             // 2048
    if (B > MAXB || K > MAXK || D != D_DIM) return;
    if (TOPK_NT * SEG < G) return;
    if (K % MT != 0) return;

    cudaFuncSetAttribute(gemm_kernel,
                         cudaFuncAttributeMaxDynamicSharedMemorySize, DYN_BYTES);

    topk_kernel<<<B, TOPK_NT>>>(expr, B, G, K);
    w2split_kernel<<<(D_DIM * D_DIM) / 256, 256>>>(w2);

    int tiles = (B * K) / MT;               // 512
    gemm_kernel<<<tiles, 256, DYN_BYTES>>>(expr, gene_emb, w1, b1, b2, out, B, G, K);

    cls_mask_kernel<<<B, 256>>>(cls, out, B, K, hasMask);
}

// round 9
// speedup vs baseline: 2.5119x; 1.0528x over previous
#include <cuda_runtime.h>
#include <cuda_bf16.h>
#include <math.h>
#include <stdint.h>

#define D_DIM 256
#define MAXB  64
#define MAXK  4096
#define TOPK_NT 1024
#define SEG   20
#define WSPLIT_BLOCKS 16

#define MT    64                  // tokens per GEMM block
#define KC    64                  // K elements per chunk
#define NCHUNK (D_DIM / KC)       // 4
#define APITCH 72                 // bf16 elems per A row in smem
#define BPITCH 72
#define A_ELEMS (MT * APITCH)     // 4608
#define B_ELEMS (D_DIM * BPITCH)  // 18432
#define SM_AHI 0
#define SM_ALO (A_ELEMS)
#define SM_BHI (2 * A_ELEMS)
#define SM_BLO (2 * A_ELEMS + B_ELEMS)
#define DYN_ELEMS (2 * A_ELEMS + 2 * B_ELEMS)      // 46080 bf16
#define DYN_BYTES (DYN_ELEMS * 2)                  // 92160 B

// scratch (no cudaMalloc allowed)
__device__ int g_sel[MAXB * MAXK];
__device__ int g_cnt[MAXB];
__device__ __nv_bfloat16 g_w2hi[D_DIM * D_DIM];
__device__ __nv_bfloat16 g_w2lo[D_DIM * D_DIM];

// ---------------- mma / ldmatrix helpers ----------------
__device__ __forceinline__ void mma_bf16(float* c, const uint32_t* a, const uint32_t* b) {
    asm volatile(
        "mma.sync.aligned.m16n8k16.row.col.f32.bf16.bf16.f32 "
        "{%0,%1,%2,%3}, {%4,%5,%6,%7}, {%8,%9}, {%0,%1,%2,%3};"
        : "+f"(c[0]), "+f"(c[1]), "+f"(c[2]), "+f"(c[3])
        : "r"(a[0]), "r"(a[1]), "r"(a[2]), "r"(a[3]), "r"(b[0]), "r"(b[1]));
}
__device__ __forceinline__ void ldm_x4(uint32_t* r, const __nv_bfloat16* p) {
    uint32_t a = (uint32_t)__cvta_generic_to_shared(p);
    asm volatile("ldmatrix.sync.aligned.m8n8.x4.shared.b16 {%0,%1,%2,%3}, [%4];"
                 : "=r"(r[0]), "=r"(r[1]), "=r"(r[2]), "=r"(r[3]) : "r"(a));
}

// ---------------- block scan (exclusive) ----------------
__device__ __forceinline__ void block_scan(int v, int& excl, int& total) {
    const int tid  = threadIdx.x;
    const int lane = tid & 31, wrp = tid >> 5;
    const int nw   = blockDim.x >> 5;
    __shared__ int wsum[32];
    int inc = v;
#pragma unroll
    for (int o = 1; o < 32; o <<= 1) {
        int n = __shfl_up_sync(0xFFFFFFFFu, inc, o);
        if (lane >= o) inc += n;
    }
    if (lane == 31) wsum[wrp] = inc;
    __syncthreads();
    if (wrp == 0) {
        int w = (lane < nw) ? wsum[lane] : 0;
#pragma unroll
        for (int o = 1; o < 32; o <<= 1) {
            int n = __shfl_up_sync(0xFFFFFFFFu, w, o);
            if (lane >= o) w += n;
        }
        wsum[lane] = w;
    }
    __syncthreads();
    int woff = wrp ? wsum[wrp - 1] : 0;
    excl  = woff + inc - v;
    total = wsum[nw - 1];
    __syncthreads();
}

// ---------------- fused: top-k + cls/mask epilogue + w2 hi/lo split ----------------
// Blocks 0..B-1: radix-select top-K of one batch row, write selection, cls row, mask.
// Blocks B..B+WSPLIT_BLOCKS-1: split w2 into bf16 hi/lo tables.
__global__ __launch_bounds__(TOPK_NT)
void topk_kernel(const float* __restrict__ expr,
                 const float* __restrict__ w2,
                 const float* __restrict__ cls,
                 float* __restrict__ out,
                 int B, int G, int K, int hasMask) {
    const int tid = threadIdx.x;

    if (blockIdx.x >= (unsigned)B) {
        // ---- w2 split path: 16 blocks x 1024 threads x 4 elems ----
        int idx = ((blockIdx.x - B) * TOPK_NT + tid) * 4;
        if (idx < D_DIM * D_DIM) {
            float4 w = *(const float4*)(&w2[idx]);
            float wv[4] = {w.x, w.y, w.z, w.w};
            uint32_t hpack[2], lpack[2];
            unsigned short hs[4], ls[4];
#pragma unroll
            for (int j = 0; j < 4; ++j) {
                __nv_bfloat16 hi = __float2bfloat16(wv[j]);
                float lo_f = wv[j] - __bfloat162float(hi);
                __nv_bfloat16 lo = __float2bfloat16(lo_f);
                hs[j] = *(unsigned short*)&hi;
                ls[j] = *(unsigned short*)&lo;
            }
            hpack[0] = hs[0] | ((uint32_t)hs[1] << 16);
            hpack[1] = hs[2] | ((uint32_t)hs[3] << 16);
            lpack[0] = ls[0] | ((uint32_t)ls[1] << 16);
            lpack[1] = ls[2] | ((uint32_t)ls[3] << 16);
            *(uint2*)(&g_w2hi[idx]) = make_uint2(hpack[0], hpack[1]);
            *(uint2*)(&g_w2lo[idx]) = make_uint2(lpack[0], lpack[1]);
        }
        return;
    }

    const int b = blockIdx.x;
    const float* __restrict__ row = expr + (size_t)b * G;

    __shared__ unsigned int hist[256];
    __shared__ unsigned int s_prefix;
    __shared__ int s_remaining;

    const int base = tid * SEG;
    unsigned keys[SEG];
    if (base + SEG <= G) {
#pragma unroll
        for (int i = 0; i < SEG; i += 4) {
            float4 v = *(const float4*)(&row[base + i]);
            keys[i + 0] = __float_as_uint(v.x);
            keys[i + 1] = __float_as_uint(v.y);
            keys[i + 2] = __float_as_uint(v.z);
            keys[i + 3] = __float_as_uint(v.w);
        }
    } else {
#pragma unroll
        for (int i = 0; i < SEG; ++i)
            keys[i] = (base + i < G) ? __float_as_uint(row[base + i]) : 0u;
    }

    if (tid == 0) { s_prefix = 0u; s_remaining = K; }
    __syncthreads();

#pragma unroll
    for (int pass = 0; pass < 4; ++pass) {
        const int shift = 24 - 8 * pass;
        const unsigned maskHigh = (pass == 0) ? 0u : (0xFFFFFFFFu << (shift + 8));
        if (tid < 256) hist[tid] = 0u;
        __syncthreads();
        const unsigned prefix = s_prefix;
        const int rem = s_remaining;
#pragma unroll
        for (int i = 0; i < SEG; ++i) {
            unsigned key = keys[i];
            if ((key & maskHigh) == prefix)
                atomicAdd(&hist[(key >> shift) & 0xFFu], 1u);
        }
        __syncthreads();
        int v = (tid < 256) ? (int)hist[255 - tid] : 0;
        int excl, total;
        block_scan(v, excl, total);
        int incl = excl + v;
        if (tid < 256 && incl >= rem && excl < rem) {
            s_prefix    = prefix | ((unsigned)(255 - tid) << shift);
            s_remaining = rem - excl;
        }
        __syncthreads();
    }
    const unsigned pivot = s_prefix;
    const int r = s_remaining;

    int n_gt = 0, n_eq = 0;
#pragma unroll
    for (int i = 0; i < SEG; ++i) {
        n_gt += (keys[i] > pivot);
        n_eq += (keys[i] == pivot);
    }
    int eq_base, eq_tot;
    block_scan(n_eq, eq_base, eq_tot);
    int eq_keep = 0;
    if (pivot > 0u) {
        int take = r - eq_base;
        eq_keep = take < 0 ? 0 : (take > n_eq ? n_eq : take);
    }
    int n_keep = n_gt + eq_keep;
    int out_base, out_tot;
    block_scan(n_keep, out_base, out_tot);

    int pos = out_base, erank = eq_base;
    int* __restrict__ sel = g_sel + b * MAXK;
#pragma unroll
    for (int i = 0; i < SEG; ++i) {
        unsigned key = keys[i];
        if (key > pivot) {
            sel[pos++] = base + i;
        } else if (key == pivot) {
            if (pivot > 0u && erank < r) sel[pos++] = base + i;
            ++erank;
        }
    }
    const int cnt = (out_tot < K) ? out_tot : K;
    if (tid == 0) g_cnt[b] = cnt;

    // ---- fused cls row + mask epilogue ----
    const size_t rowsz = (size_t)(K + 1) * D_DIM;
    float* orow = out + (size_t)b * rowsz;
    if (tid < D_DIM) orow[tid] = cls[tid];
    if (hasMask) {
        float* mask = out + (size_t)B * rowsz + (size_t)b * (K + 1);
        for (int j = tid; j < K + 1; j += TOPK_NT)
            mask[j] = (j == 0 || (j - 1) < cnt) ? 1.0f : 0.0f;
    }
}

// ---------------- token GEMM via mma.sync bf16 (3-pass hi/lo, ldmatrix) ----------------
// Block: 256 threads = 8 warps (2 x 4). Block tile 64 tokens x 256 outputs.
// Warp tile: 32 tokens x 64 outputs. K = 256 in 4 chunks of 64.
__global__ __launch_bounds__(256, 2)
void gemm_kernel(const float* __restrict__ expr,
                 const float* __restrict__ gene_emb,
                 const float* __restrict__ w1,
                 const float* __restrict__ b1,
                 const float* __restrict__ b2,
                 float* __restrict__ out,
                 int B, int G, int K) {
    extern __shared__ __nv_bfloat16 sm[];
    __nv_bfloat16* const sAhi = sm + SM_AHI;
    __nv_bfloat16* const sAlo = sm + SM_ALO;
    __nv_bfloat16* const sBhi = sm + SM_BHI;
    __nv_bfloat16* const sBlo = sm + SM_BLO;

    __shared__ float sx[MT];
    __shared__ int   sgm[MT];
    __shared__ float sw1[D_DIM], sb1[D_DIM], sb2[D_DIM];

    const int tid  = threadIdx.x;
    const int wid  = tid >> 5, lane = tid & 31;
    const int wm   = wid >> 2;            // 0..1 (token dim)
    const int wn   = wid & 3;             // 0..3 (output dim)
    const int gr   = lane >> 2;           // groupID 0..7
    const int cq   = lane & 3;            // threadID-in-group
    const int t0   = blockIdx.x * MT;
    const int bb   = t0 / K;              // K % MT == 0

    if (tid < MT) {
        int k = t0 - bb * K + tid;
        int g = -1; float x = 0.0f;
        if (bb < B && k < g_cnt[bb]) {
            g = g_sel[bb * MAXK + k];
            x = expr[(size_t)bb * G + g];
        }
        sgm[tid] = g; sx[tid] = x;
    }
    sw1[tid] = w1[tid];
    sb1[tid] = b1[tid];
    sb2[tid] = b2[tid];
    __syncthreads();

    float acc[2][8][4];
#pragma unroll
    for (int mi = 0; mi < 2; ++mi)
#pragma unroll
        for (int ni = 0; ni < 8; ++ni)
#pragma unroll
            for (int j = 0; j < 4; ++j) acc[mi][ni][j] = 0.0f;

    const int at = tid >> 2;              // token row for A fill (0..63)
    const int akq = tid & 3;              // k quarter (16 elems)
    const float ax = sx[at];

    // ldmatrix per-lane tile-row offsets (element units)
    const int a_row = wm * 32 + ((lane >> 3) & 1) * 8 + (lane & 7);
    const int a_kof = (lane >> 4) * 8;
    const int b_rof = ((lane >> 4) & 1) * 8 + (lane & 7);
    const int b_kof = ((lane >> 3) & 1) * 8;

    for (int c = 0; c < NCHUNK; ++c) {
        const int d0 = c * KC;
        // --- A fill: h = gelu(x*w1+b1), split hi/lo. 16 elems/thread ---
#pragma unroll
        for (int j = 0; j < 16; ++j) {
            int kk = akq * 16 + j;
            int d  = d0 + kk;
            float z = fmaf(ax, sw1[d], sb1[d]);
            float h = 0.5f * z * (1.0f + erff(z * 0.70710678118654752f));
            __nv_bfloat16 hi = __float2bfloat16(h);
            float lo_f = h - __bfloat162float(hi);
            sAhi[at * APITCH + kk] = hi;
            sAlo[at * APITCH + kk] = __float2bfloat16(lo_f);
        }
        // --- B fill: copy precomputed w2 hi/lo chunk. [n][k] layout ---
#pragma unroll
        for (int i = 0; i < 8; ++i) {
            int n   = i * 32 + (tid >> 3);
            int k16 = (tid & 7) * 8;      // 8 bf16 = 16 B
            uint4 vhi = *(const uint4*)(&g_w2hi[(size_t)n * D_DIM + d0 + k16]);
            uint4 vlo = *(const uint4*)(&g_w2lo[(size_t)n * D_DIM + d0 + k16]);
            *(uint4*)(&sBhi[n * BPITCH + k16]) = vhi;
            *(uint4*)(&sBlo[n * BPITCH + k16]) = vlo;
        }
        __syncthreads();

        // --- mainloop: 4 k-steps of 16 (ldmatrix fragment loads) ---
#pragma unroll
        for (int ks = 0; ks < 4; ++ks) {
            const int kb = ks * 16;
            uint32_t ahi[2][4], alo[2][4];
#pragma unroll
            for (int mi = 0; mi < 2; ++mi) {
                const int aoff = (a_row + mi * 16) * APITCH + kb + a_kof;
                ldm_x4(ahi[mi], sAhi + aoff);
                ldm_x4(alo[mi], sAlo + aoff);
            }
#pragma unroll
            for (int p = 0; p < 4; ++p) {
                const int boff = (wn * 64 + p * 16 + b_rof) * BPITCH + kb + b_kof;
                uint32_t bh[4], bl[4];
                ldm_x4(bh, sBhi + boff);
                ldm_x4(bl, sBlo + boff);
#pragma unroll
                for (int half = 0; half < 2; ++half) {
                    const int ni = p * 2 + half;
                    const uint32_t* bhv = bh + half * 2;
                    const uint32_t* blv = bl + half * 2;
#pragma unroll
                    for (int mi = 0; mi < 2; ++mi) {
                        mma_bf16(acc[mi][ni], ahi[mi], bhv);
                        mma_bf16(acc[mi][ni], ahi[mi], blv);
                        mma_bf16(acc[mi][ni], alo[mi], bhv);
                    }
                }
            }
        }
        __syncthreads();
    }

    // ---------------- epilogue ----------------
#pragma unroll
    for (int mi = 0; mi < 2; ++mi) {
#pragma unroll
        for (int half = 0; half < 2; ++half) {
            int t_local = wm * 32 + mi * 16 + gr + half * 8;
            int g = sgm[t_local];
            int tk = t0 + t_local;
            int k_in = tk - bb * K;
            size_t rowoff = ((size_t)bb * (K + 1) + (k_in + 1)) * D_DIM;
#pragma unroll
            for (int ni = 0; ni < 8; ++ni) {
                int e = wn * 64 + ni * 8 + 2 * cq;
                float c0 = acc[mi][ni][half * 2 + 0];
                float c1 = acc[mi][ni][half * 2 + 1];
                float2 v;
                if (g >= 0) {
                    float2 ge = *(const float2*)(&gene_emb[(size_t)g * D_DIM + e]);
                    v.x = c0 + ge.x + sb2[e + 0];
                    v.y = c1 + ge.y + sb2[e + 1];
                } else {
                    v = make_float2(0.f, 0.f);
                }
                *(float2*)(&out[rowoff + e]) = v;
            }
        }
    }
}

extern "C" void kernel_launch(void* const* d_in, const int* in_sizes, int n_in,
                              void* d_out, int out_size) {
    const float* expr     = (const float*)d_in[0];
    const float* gene_emb = (const float*)d_in[1];
    const float* w1       = (const float*)d_in[2];
    const float* b1       = (const float*)d_in[3];
    const float* w2       = (const float*)d_in[4];
    const float* b2       = (const float*)d_in[5];
    const float* cls      = (const float*)d_in[6];
    float* out = (float*)d_out;

    const int D = in_sizes[2];              // 256
    const int G = in_sizes[1] / D;          // 20000
    const int B = in_sizes[0] / G;          // 16

    long Kp1; int hasMask;
    if (out_size % ((long)B * (D + 1)) == 0) {
        Kp1 = out_size / ((long)B * (D + 1));
        hasMask = 1;
    } else {
        Kp1 = out_size / ((long)B * D);
        hasMask = 0;
    }
    const int K = (int)Kp1 - 1;             // 2048
    if (B > MAXB || K > MAXK || D != D_DIM) return;
    if (TOPK_NT * SEG < G) return;
    if (K % MT != 0) return;

    cudaFuncSetAttribute(gemm_kernel,
                         cudaFuncAttributeMaxDynamicSharedMemorySize, DYN_BYTES);

    topk_kernel<<<B + WSPLIT_BLOCKS, TOPK_NT>>>(expr, w2, cls, out, B, G, K, hasMask);

    int tiles = (B * K) / MT;               // 512
    gemm_kernel<<<tiles, 256, DYN_BYTES>>>(expr, gene_emb, w1, b1, b2, out, B, G, K);
}